// round 4
// baseline (speedup 1.0000x reference)
#include <cuda_runtime.h>
#include <cstdint>

// ---------------------------------------------------------------------------
// GCN: 4 layers, N=100000, E=1600000, 128->128->128->128->64
//   - preprocessing: degree + rsqrt + CSR-by-dst (count/scan/place)
//   - per layer: packed-f32x2 SGEMM (128x128 tile, 8x8 micro, FFMA2)
//                then warp-per-node aggregation (fused bias+relu, no atomics)
// ---------------------------------------------------------------------------

#define N_NODES 100000
#define N_EDGES 1600000
#define DIM 128

// ----------------------------- scratch --------------------------------------
__device__ float g_deg[N_NODES];
__device__ float g_dinv[N_NODES];
__device__ float g_self[N_NODES];
__device__ int   g_counts[N_NODES];
__device__ int   g_offsets[N_NODES + 1];
__device__ int   g_cursor[N_NODES];
__device__ int   g_blocksums[256];
__device__ int2  g_edges[N_EDGES];          // {src, norm bits} interleaved
__device__ float g_bufA[(size_t)N_NODES * DIM];
__device__ float g_bufB[(size_t)N_NODES * DIM];

// ----------------------------- f32x2 helpers --------------------------------
__device__ __forceinline__ void ffma2(unsigned long long& acc,
                                      unsigned long long a,
                                      unsigned long long b) {
    asm("fma.rn.f32x2 %0, %1, %2, %0;" : "+l"(acc) : "l"(a), "l"(b));
}
__device__ __forceinline__ unsigned long long dup2(float v) {
    unsigned long long r;
    unsigned int u = __float_as_uint(v);
    asm("mov.b64 %0, {%1, %1};" : "=l"(r) : "r"(u));
    return r;
}
__device__ __forceinline__ void unpack2(unsigned long long p, float& lo, float& hi) {
    unsigned int a, b;
    asm("mov.b64 {%0, %1}, %2;" : "=r"(a), "=r"(b) : "l"(p));
    lo = __uint_as_float(a);
    hi = __uint_as_float(b);
}

// ----------------------------- preprocessing --------------------------------
__global__ void k_init_nodes() {
    int i = blockIdx.x * blockDim.x + threadIdx.x;
    if (i < N_NODES) {
        g_deg[i]    = 1.0f;   // self-loop weight
        g_counts[i] = 0;
        g_cursor[i] = 0;
    }
}

__global__ void k_edge_degree(const int* __restrict__ ei, const float* __restrict__ w) {
    int e = blockIdx.x * blockDim.x + threadIdx.x;
    if (e < N_EDGES) {
        int dst = ei[N_EDGES + e];
        atomicAdd(&g_deg[dst], w[e]);
        atomicAdd(&g_counts[dst], 1);
    }
}

__global__ void k_dinv() {
    int i = blockIdx.x * blockDim.x + threadIdx.x;
    if (i < N_NODES) {
        float d = g_deg[i];
        float r = (d > 0.0f) ? rsqrtf(d) : 0.0f;
        g_dinv[i] = r;
        g_self[i] = r * r;
    }
}

#define SCAN_BS 1024
__global__ void k_scanA() {
    __shared__ int s[SCAN_BS];
    int t = threadIdx.x;
    int i = blockIdx.x * SCAN_BS + t;
    int v = (i < N_NODES) ? g_counts[i] : 0;
    s[t] = v;
    __syncthreads();
    for (int off = 1; off < SCAN_BS; off <<= 1) {
        int x = (t >= off) ? s[t - off] : 0;
        __syncthreads();
        s[t] += x;
        __syncthreads();
    }
    if (i < N_NODES) g_offsets[i + 1] = s[t];
    if (t == SCAN_BS - 1) g_blocksums[blockIdx.x] = s[t];
}

__global__ void k_scanB(int nblocks) {
    if (threadIdx.x == 0 && blockIdx.x == 0) {
        int run = 0;
        for (int b = 0; b < nblocks; b++) {
            int v = g_blocksums[b];
            g_blocksums[b] = run;
            run += v;
        }
    }
}

__global__ void k_scanC() {
    int t = threadIdx.x;
    int i = blockIdx.x * SCAN_BS + t;
    if (i < N_NODES) g_offsets[i + 1] += g_blocksums[blockIdx.x];
    if (i == 0) g_offsets[0] = 0;
}

__global__ void k_place(const int* __restrict__ ei, const float* __restrict__ w) {
    int e = blockIdx.x * blockDim.x + threadIdx.x;
    if (e < N_EDGES) {
        int src = ei[e];
        int dst = ei[N_EDGES + e];
        int pos = g_offsets[dst] + atomicAdd(&g_cursor[dst], 1);
        float nm = g_dinv[src] * w[e] * g_dinv[dst];
        g_edges[pos] = make_int2(src, __float_as_int(nm));
    }
}

// ----------------------------- packed-f32x2 SGEMM ----------------------------
// out[N, DOUT] = X[N,128] @ W[128, DOUT].  Tile 128 x DOUT, 256 threads.
// Micro-tile per thread: 8 rows x MC cols, accumulators packed along row pairs.
template <int DOUT>
__global__ void __launch_bounds__(256, 2) k_gemm2(const float* __restrict__ X,
                                                  const float* __restrict__ W,
                                                  float* __restrict__ out) {
    constexpr int KT   = 16;            // K tile
    constexpr int MC   = DOUT / 16;     // micro cols per thread: 8 or 4
    constexpr int NWLD = DOUT / 64;     // W float4 loads/thread/tile: 2 or 1

    __shared__ __align__(16) float xs[KT][132];     // [k][row] transposed
    __shared__ __align__(16) float ws[KT][DOUT];    // [k][col]

    const int tid  = threadIdx.x;
    const int row0 = blockIdx.x * 128;
    const int tm   = tid >> 4;          // 0..15: rows tm*8..tm*8+7
    const int tn   = tid & 15;          // 0..15: cols tn*MC..tn*MC+MC-1

    unsigned long long acc[4][MC];
#pragma unroll
    for (int rp = 0; rp < 4; rp++)
#pragma unroll
        for (int c = 0; c < MC; c++) acc[rp][c] = 0ull;

    float4 xr[2];
    float4 wr[NWLD];

    // ---- prologue: load k-tile 0 into registers ----
#pragma unroll
    for (int i = 0; i < 2; i++) {
        int s = tid + i * 256;
        int r = s >> 2;
        int k4 = (s & 3) * 4;
        int grow = row0 + r;
        xr[i] = make_float4(0.f, 0.f, 0.f, 0.f);
        if (grow < N_NODES)
            xr[i] = *reinterpret_cast<const float4*>(&X[(size_t)grow * DIM + k4]);
    }
#pragma unroll
    for (int i = 0; i < NWLD; i++) {
        int s = tid + i * 256;
        int k, c4;
        if (DOUT == 128) { k = s >> 5; c4 = (s & 31) * 4; }
        else             { k = s >> 4; c4 = (s & 15) * 4; }
        wr[i] = *reinterpret_cast<const float4*>(&W[(size_t)k * DOUT + c4]);
    }

    for (int kt = 0; kt < 8; kt++) {
        // store prefetched registers to smem
#pragma unroll
        for (int i = 0; i < 2; i++) {
            int s = tid + i * 256;
            int r = s >> 2;
            int k4 = (s & 3) * 4;
            xs[k4 + 0][r] = xr[i].x;
            xs[k4 + 1][r] = xr[i].y;
            xs[k4 + 2][r] = xr[i].z;
            xs[k4 + 3][r] = xr[i].w;
        }
#pragma unroll
        for (int i = 0; i < NWLD; i++) {
            int s = tid + i * 256;
            int k, c4;
            if (DOUT == 128) { k = s >> 5; c4 = (s & 31) * 4; }
            else             { k = s >> 4; c4 = (s & 15) * 4; }
            *reinterpret_cast<float4*>(&ws[k][c4]) = wr[i];
        }
        __syncthreads();

        // prefetch next k-tile
        if (kt < 7) {
            int kbase = (kt + 1) * KT;
#pragma unroll
            for (int i = 0; i < 2; i++) {
                int s = tid + i * 256;
                int r = s >> 2;
                int k4 = (s & 3) * 4;
                int grow = row0 + r;
                xr[i] = make_float4(0.f, 0.f, 0.f, 0.f);
                if (grow < N_NODES)
                    xr[i] = *reinterpret_cast<const float4*>(
                        &X[(size_t)grow * DIM + kbase + k4]);
            }
#pragma unroll
            for (int i = 0; i < NWLD; i++) {
                int s = tid + i * 256;
                int k, c4;
                if (DOUT == 128) { k = s >> 5; c4 = (s & 31) * 4; }
                else             { k = s >> 4; c4 = (s & 15) * 4; }
                wr[i] = *reinterpret_cast<const float4*>(
                    &W[(size_t)(kbase + k) * DOUT + c4]);
            }
        }

        // compute on current smem tile
#pragma unroll
        for (int k = 0; k < KT; k++) {
            ulonglong2 A0 = *reinterpret_cast<const ulonglong2*>(&xs[k][tm * 8]);
            ulonglong2 A1 = *reinterpret_cast<const ulonglong2*>(&xs[k][tm * 8 + 4]);
            unsigned long long ap[4] = {A0.x, A0.y, A1.x, A1.y};

            unsigned long long bd[MC];
            float4 b0 = *reinterpret_cast<const float4*>(&ws[k][tn * MC]);
            bd[0] = dup2(b0.x); bd[1] = dup2(b0.y);
            bd[2] = dup2(b0.z); bd[3] = dup2(b0.w);
            if (MC == 8) {
                float4 b1 = *reinterpret_cast<const float4*>(&ws[k][tn * MC + 4]);
                bd[4] = dup2(b1.x); bd[5] = dup2(b1.y);
                bd[6] = dup2(b1.z); bd[7] = dup2(b1.w);
            }
#pragma unroll
            for (int rp = 0; rp < 4; rp++)
#pragma unroll
                for (int c = 0; c < MC; c++) ffma2(acc[rp][c], ap[rp], bd[c]);
        }
        __syncthreads();
    }

    // ---- epilogue: unpack + store ----
#pragma unroll
    for (int rp = 0; rp < 4; rp++) {
        float vlo[MC], vhi[MC];
#pragma unroll
        for (int c = 0; c < MC; c++) unpack2(acc[rp][c], vlo[c], vhi[c]);
        int g0 = row0 + tm * 8 + rp * 2;
        if (g0 < N_NODES) {
            float* p = &out[(size_t)g0 * DOUT + tn * MC];
            *reinterpret_cast<float4*>(p) = make_float4(vlo[0], vlo[1], vlo[2], vlo[3]);
            if (MC == 8)
                *reinterpret_cast<float4*>(p + 4) = make_float4(vlo[4], vlo[5], vlo[6], vlo[7]);
        }
        if (g0 + 1 < N_NODES) {
            float* p = &out[(size_t)(g0 + 1) * DOUT + tn * MC];
            *reinterpret_cast<float4*>(p) = make_float4(vhi[0], vhi[1], vhi[2], vhi[3]);
            if (MC == 8)
                *reinterpret_cast<float4*>(p + 4) = make_float4(vhi[4], vhi[5], vhi[6], vhi[7]);
        }
    }
}

// ----------------------------- aggregation: warp per node -------------------
// out[i] = bias + self[i]*h[i] + sum_{j in CSR[i]} norm[j] * h[src[j]]
template <int DOUT, bool RELU>
__global__ void __launch_bounds__(256) k_agg(const float* __restrict__ H,
                                             const float* __restrict__ bias,
                                             float* __restrict__ out) {
    int node = (blockIdx.x * blockDim.x + threadIdx.x) >> 5;
    int lane = threadIdx.x & 31;
    if (node >= N_NODES) return;

    constexpr int V = DOUT / 32;   // 4 (128) or 2 (64)

    float acc[V];
    float s = g_self[node];
    if constexpr (V == 4) {
        float4 h = *reinterpret_cast<const float4*>(&H[(size_t)node * DOUT + lane * 4]);
        acc[0] = s * h.x; acc[1] = s * h.y; acc[2] = s * h.z; acc[3] = s * h.w;
    } else {
        float2 h = *reinterpret_cast<const float2*>(&H[(size_t)node * DOUT + lane * 2]);
        acc[0] = s * h.x; acc[1] = s * h.y;
    }

    const int2* __restrict__ ep = g_edges;
    int beg = g_offsets[node];
    int end = g_offsets[node + 1];

    int j = beg;
    for (; j + 4 <= end; j += 4) {
        int2 e0 = ep[j], e1 = ep[j + 1], e2 = ep[j + 2], e3 = ep[j + 3];
        float n0 = __int_as_float(e0.y), n1 = __int_as_float(e1.y);
        float n2 = __int_as_float(e2.y), n3 = __int_as_float(e3.y);
        if constexpr (V == 4) {
            float4 h0 = *reinterpret_cast<const float4*>(&H[(size_t)e0.x * DOUT + lane * 4]);
            float4 h1 = *reinterpret_cast<const float4*>(&H[(size_t)e1.x * DOUT + lane * 4]);
            float4 h2 = *reinterpret_cast<const float4*>(&H[(size_t)e2.x * DOUT + lane * 4]);
            float4 h3 = *reinterpret_cast<const float4*>(&H[(size_t)e3.x * DOUT + lane * 4]);
            acc[0] += n0 * h0.x; acc[1] += n0 * h0.y; acc[2] += n0 * h0.z; acc[3] += n0 * h0.w;
            acc[0] += n1 * h1.x; acc[1] += n1 * h1.y; acc[2] += n1 * h1.z; acc[3] += n1 * h1.w;
            acc[0] += n2 * h2.x; acc[1] += n2 * h2.y; acc[2] += n2 * h2.z; acc[3] += n2 * h2.w;
            acc[0] += n3 * h3.x; acc[1] += n3 * h3.y; acc[2] += n3 * h3.z; acc[3] += n3 * h3.w;
        } else {
            float2 h0 = *reinterpret_cast<const float2*>(&H[(size_t)e0.x * DOUT + lane * 2]);
            float2 h1 = *reinterpret_cast<const float2*>(&H[(size_t)e1.x * DOUT + lane * 2]);
            float2 h2 = *reinterpret_cast<const float2*>(&H[(size_t)e2.x * DOUT + lane * 2]);
            float2 h3 = *reinterpret_cast<const float2*>(&H[(size_t)e3.x * DOUT + lane * 2]);
            acc[0] += n0 * h0.x; acc[1] += n0 * h0.y;
            acc[0] += n1 * h1.x; acc[1] += n1 * h1.y;
            acc[0] += n2 * h2.x; acc[1] += n2 * h2.y;
            acc[0] += n3 * h3.x; acc[1] += n3 * h3.y;
        }
    }
    for (; j < end; j++) {
        int2 e = ep[j];
        float nm = __int_as_float(e.y);
        if constexpr (V == 4) {
            float4 h = *reinterpret_cast<const float4*>(&H[(size_t)e.x * DOUT + lane * 4]);
            acc[0] += nm * h.x; acc[1] += nm * h.y; acc[2] += nm * h.z; acc[3] += nm * h.w;
        } else {
            float2 h = *reinterpret_cast<const float2*>(&H[(size_t)e.x * DOUT + lane * 2]);
            acc[0] += nm * h.x; acc[1] += nm * h.y;
        }
    }

    if constexpr (V == 4) {
        float4 b = *reinterpret_cast<const float4*>(&bias[lane * 4]);
        acc[0] += b.x; acc[1] += b.y; acc[2] += b.z; acc[3] += b.w;
        if (RELU) {
#pragma unroll
            for (int c = 0; c < 4; c++) acc[c] = fmaxf(acc[c], 0.0f);
        }
        *reinterpret_cast<float4*>(&out[(size_t)node * DOUT + lane * 4]) =
            make_float4(acc[0], acc[1], acc[2], acc[3]);
    } else {
        float2 b = *reinterpret_cast<const float2*>(&bias[lane * 2]);
        acc[0] += b.x; acc[1] += b.y;
        if (RELU) {
            acc[0] = fmaxf(acc[0], 0.0f);
            acc[1] = fmaxf(acc[1], 0.0f);
        }
        *reinterpret_cast<float2*>(&out[(size_t)node * DOUT + lane * 2]) =
            make_float2(acc[0], acc[1]);
    }
}

// ----------------------------- launch ---------------------------------------
extern "C" void kernel_launch(void* const* d_in, const int* in_sizes, int n_in,
                              void* d_out, int out_size) {
    const float* x  = (const float*)d_in[0];
    const float* ew = (const float*)d_in[1];
    const int*   ei = (const int*)d_in[2];
    const float* W1 = (const float*)d_in[3];
    const float* b1 = (const float*)d_in[4];
    const float* W2 = (const float*)d_in[5];
    const float* b2 = (const float*)d_in[6];
    const float* W3 = (const float*)d_in[7];
    const float* b3 = (const float*)d_in[8];
    const float* W4 = (const float*)d_in[9];
    const float* b4 = (const float*)d_in[10];
    float* out = (float*)d_out;

    float *bufA, *bufB;
    cudaGetSymbolAddress((void**)&bufA, g_bufA);
    cudaGetSymbolAddress((void**)&bufB, g_bufB);

    const int NB_N  = (N_NODES + 255) / 256;
    const int NB_E  = (N_EDGES + 255) / 256;
    const int NB_SC = (N_NODES + SCAN_BS - 1) / SCAN_BS;

    // ---- preprocessing ----
    k_init_nodes<<<NB_N, 256>>>();
    k_edge_degree<<<NB_E, 256>>>(ei, ew);
    k_dinv<<<NB_N, 256>>>();
    k_scanA<<<NB_SC, SCAN_BS>>>();
    k_scanB<<<1, 32>>>(NB_SC);
    k_scanC<<<NB_SC, SCAN_BS>>>();
    k_place<<<NB_E, 256>>>(ei, ew);

    // ---- layers ----
    const int GEMM_BLOCKS = (N_NODES + 127) / 128;
    const int AGG_BLOCKS  = (N_NODES * 32 + 255) / 256;   // warp per node

    k_gemm2<128><<<GEMM_BLOCKS, 256>>>(x, W1, bufA);
    k_agg<128, true><<<AGG_BLOCKS, 256>>>(bufA, b1, bufB);

    k_gemm2<128><<<GEMM_BLOCKS, 256>>>(bufB, W2, bufA);
    k_agg<128, true><<<AGG_BLOCKS, 256>>>(bufA, b2, bufB);

    k_gemm2<128><<<GEMM_BLOCKS, 256>>>(bufB, W3, bufA);
    k_agg<128, true><<<AGG_BLOCKS, 256>>>(bufA, b3, bufB);

    k_gemm2<64><<<GEMM_BLOCKS, 256>>>(bufB, W4, bufA);
    k_agg<64, false><<<AGG_BLOCKS, 256>>>(bufA, b4, out);
}